// round 3
// baseline (speedup 1.0000x reference)
#include <cuda_runtime.h>
#include <math.h>

#define HOR   256
#define EPSV  0.001f

// ---------------- device-global precomputed weights (transposed: [k][f]) ----------------
__device__ float g_C1T [64*64];
__device__ float g_FT  [64*64];
__device__ float g_D11T[64*64];
__device__ float g_B1T [64*64];
__device__ float g_EinvT[64*64];
__device__ float g_D12T[32*64];
__device__ float g_B2T [32*64];
__device__ float g_D22T[32*32];
__device__ float g_D21T[64*32];
__device__ float g_C2T [64*32];
__device__ float g_invLam[64];
__device__ float g_E   [64*64];

// ---------------- kernel 1: derived matrices from X, Y + input transposes ----------------
__global__ void ren_precompute(const float* __restrict__ X, const float* __restrict__ Y,
                               const float* __restrict__ B2, const float* __restrict__ C2,
                               const float* __restrict__ D21, const float* __restrict__ D22,
                               const float* __restrict__ D12) {
    int gid = blockIdx.x * blockDim.x + threadIdx.x;
    if (gid >= 4096) return;
    int f = gid >> 6, k = gid & 63;

    // H(a,b) = sum_j X[j][a]*X[j][b]  (+ eps on diagonal). Compute the 6 blocks we need.
    float s11 = 0.f, s21 = 0.f, s22 = 0.f, s31 = 0.f, s32 = 0.f, s33 = 0.f;
    for (int j = 0; j < 192; j++) {
        const float* row = X + j * 192;
        float a0 = row[f], a1 = row[64 + f], a2 = row[128 + f];
        float b0 = row[k], b1 = row[64 + k], b2 = row[128 + k];
        s11 += a0 * b0;   // H11(f,k)
        s21 += a1 * b0;   // H21(f,k)
        s22 += a1 * b1;   // H22(f,k)
        s31 += a2 * b0;   // H31(f,k)
        s32 += a2 * b1;   // H32(f,k)
        s33 += a2 * b2;   // H33(f,k)
    }
    g_C1T [k*64 + f] = -s21;                    // C1 = -H21
    g_FT  [k*64 + f] =  s31;                    // F  =  H31
    g_B1T [k*64 + f] =  s32;                    // B1 =  H32
    g_D11T[k*64 + f] = (k < f) ? -s22 : 0.f;    // D11 = -tril(H22,-1)

    float diag = (f == k) ? EPSV : 0.f;
    if (f == k) g_invLam[f] = 2.0f / (s22 + EPSV);   // Lam = 0.5*diag(H22)
    g_E[f*64 + k] = 0.5f * ((s11 + diag) + (s33 + diag) + Y[f*64 + k] - Y[k*64 + f]);

    if (gid < 2048) {
        int ff = gid & 63, kk = gid >> 6;            // kk < 32
        g_B2T [kk*64 + ff] = B2 [ff*32 + kk];
        g_D12T[kk*64 + ff] = D12[ff*32 + kk];
        int f2 = gid & 31, k2 = gid >> 5;            // k2 < 64
        g_D21T[k2*32 + f2] = D21[f2*64 + k2];
        g_C2T [k2*32 + f2] = C2 [f2*64 + k2];
    }
    if (gid < 1024) {
        int f3 = gid & 31, k3 = gid >> 5;            // k3 < 32
        g_D22T[k3*32 + f3] = D22[f3*32 + k3];
    }
}

// ---------------- kernel 2: Gauss-Jordan inversion of E (fp32, partial pivoting) ----------------
__global__ void ren_invert() {
    __shared__ float W[64 * 128];   // [E | I]
    __shared__ int s_piv;
    int tid = threadIdx.x;

    for (int e = tid; e < 64 * 128; e += 256) {
        int r = e >> 7, c = e & 127;
        W[e] = (c < 64) ? g_E[r*64 + c] : ((c - 64 == r) ? 1.f : 0.f);
    }
    __syncthreads();

    for (int col = 0; col < 64; col++) {
        // warp-parallel argmax pivot over rows [col, 64)
        if (tid < 32) {
            int   r0 = col + tid;
            float b0 = (r0 < 64) ? fabsf(W[r0*128 + col]) : -1.f;
            int   r1 = r0 + 32;
            float b1 = (r1 < 64) ? fabsf(W[r1*128 + col]) : -1.f;
            if (b1 > b0) { b0 = b1; r0 = r1; }
            for (int off = 16; off > 0; off >>= 1) {
                float ob = __shfl_down_sync(0xffffffffu, b0, off);
                int   orr = __shfl_down_sync(0xffffffffu, r0, off);
                if (ob > b0) { b0 = ob; r0 = orr; }
            }
            if (tid == 0) s_piv = r0;
        }
        __syncthreads();
        int p = s_piv;
        if (p != col && tid < 128) {
            float tmp = W[col*128 + tid];
            W[col*128 + tid] = W[p*128 + tid];
            W[p*128 + tid] = tmp;
        }
        __syncthreads();
        float pivinv = 1.f / W[col*128 + col];
        __syncthreads();
        if (tid < 128) W[col*128 + tid] *= pivinv;
        __syncthreads();

        float fac[32];
        #pragma unroll
        for (int kk = 0; kk < 32; kk++) {
            int e = tid + kk * 256; int r = e >> 7;
            fac[kk] = (r == col) ? 0.f : W[r*128 + col];
        }
        __syncthreads();
        #pragma unroll
        for (int kk = 0; kk < 32; kk++) {
            int e = tid + kk * 256; int c = e & 127;
            W[e] -= fac[kk] * W[col*128 + c];
        }
        __syncthreads();
    }

    for (int e = tid; e < 4096; e += 256) {
        int f = e >> 6, k = e & 63;
        g_EinvT[k*64 + f] = W[f*128 + 64 + k];   // EinvT[k][f] = Einv[f][k]
    }
}

// ---------------- kernel 3: main recurrence — one warp per batch element ----------------
// lane owns feature pair (2*lane, 2*lane+1); all weights in shared (float2, conflict-free).
__global__ void __launch_bounds__(256, 1)
ren_main(const float* __restrict__ u_in, float* __restrict__ out) {
    extern __shared__ float sm[];
    float* sC1T  = sm;            // 4096
    float* sFT   = sm + 4096;     // 4096
    float* sD11T = sm + 8192;     // 4096
    float* sB1T  = sm + 12288;    // 4096
    float* sEiT  = sm + 16384;    // 4096
    float* sD12T = sm + 20480;    // 2048
    float* sB2T  = sm + 22528;    // 2048
    float* sD22T = sm + 24576;    // 1024
    float* sD21T = sm + 25600;    // 2048
    float* sC2T  = sm + 27648;    // 2048
    float* sIL   = sm + 29696;    // 64
    float* sX    = sm + 29760;    // 8*64
    float* sT    = sm + 30272;    // 8*64  (total 30784 floats = 123136 B)

    int tid = threadIdx.x;
    for (int i = tid; i < 4096; i += 256) {
        sC1T[i] = g_C1T[i]; sFT[i] = g_FT[i]; sD11T[i] = g_D11T[i];
        sB1T[i] = g_B1T[i]; sEiT[i] = g_EinvT[i];
    }
    for (int i = tid; i < 2048; i += 256) {
        sD12T[i] = g_D12T[i]; sB2T[i] = g_B2T[i];
        sD21T[i] = g_D21T[i]; sC2T[i] = g_C2T[i];
    }
    for (int i = tid; i < 1024; i += 256) sD22T[i] = g_D22T[i];
    if (tid < 64) sIL[tid] = g_invLam[tid];
    __syncthreads();

    int warp = tid >> 5, lane = tid & 31;
    int b = blockIdx.x * 8 + warp;
    float* myX = sX + warp * 64;
    float* myT = sT + warp * 64;

    const float2* C1T2  = (const float2*)sC1T;
    const float2* FT2   = (const float2*)sFT;
    const float2* D11T2 = (const float2*)sD11T;
    const float2* B1T2  = (const float2*)sB1T;
    const float2* EiT2  = (const float2*)sEiT;
    const float2* D12T2 = (const float2*)sD12T;
    const float2* B2T2  = (const float2*)sB2T;
    const float2* D22T2 = (const float2*)sD22T;
    const float2* D21T2 = (const float2*)sD21T;
    const float2* C2T2  = (const float2*)sC2T;

    ((float2*)myX)[lane] = make_float2(0.f, 0.f);   // x0 = 0
    __syncwarp();

    const float* uptr = u_in + (size_t)b * (HOR * 32) + lane;
    float*       optr = out  + (size_t)b * (HOR * 32) + 2 * lane;

    for (int t = 0; t < HOR; t++) {
        float u = uptr[t * 32];                      // u_t[lane], coalesced

        float2 pre = make_float2(0.f, 0.f);          // xC + uD, later the w accumulator
        float2 tv  = make_float2(0.f, 0.f);          // x@F^T + w@B1^T + u@B2^T
        float2 ya  = make_float2(0.f, 0.f);          // y partials (lanes 0..15, feats 0..31)

        // ---- x-dots: xC and xF ----
        #pragma unroll
        for (int k = 0; k < 64; k++) {
            float xk = myX[k];
            float2 c  = C1T2[k*32 + lane]; pre.x += c.x  * xk; pre.y += c.y  * xk;
            float2 fm = FT2 [k*32 + lane]; tv.x  += fm.x * xk; tv.y  += fm.y * xk;
        }
        // ---- u-dots: uD12, uB2, uD22 ----
        #pragma unroll
        for (int k = 0; k < 32; k++) {
            float uk = __shfl_sync(0xffffffffu, u, k);
            float2 d  = D12T2[k*32 + lane]; pre.x += d.x  * uk; pre.y += d.y  * uk;
            float2 bb = B2T2 [k*32 + lane]; tv.x  += bb.x * uk; tv.y  += bb.y * uk;
            if (lane < 16) { float2 dd = D22T2[k*16 + lane]; ya.x += dd.x * uk; ya.y += dd.y * uk; }
        }
        // ---- sequential w recurrence with on-the-fly rank-1 updates ----
        #pragma unroll
        for (int i = 0; i < 64; i++) {
            float accsel = (i & 1) ? pre.y : pre.x;
            float v  = __shfl_sync(0xffffffffu, accsel, i >> 1);  // v_i (uniform)
            float wi = tanhf(v * sIL[i]);                          // uniform tanh
            float2 d11 = D11T2[i*32 + lane]; pre.x += d11.x * wi; pre.y += d11.y * wi; // zero for f<=i
            float2 b1  = B1T2 [i*32 + lane]; tv.x  += b1.x  * wi; tv.y  += b1.y  * wi; // w@B1^T
            if (lane < 16) { float2 d21 = D21T2[i*16 + lane]; ya.x += d21.x * wi; ya.y += d21.y * wi; }
        }
        // ---- x_new = t @ Einv^T ----
        __syncwarp();
        ((float2*)myT)[lane] = tv;
        __syncwarp();
        float2 xn = make_float2(0.f, 0.f);
        #pragma unroll
        for (int k = 0; k < 64; k++) {
            float tk = myT[k];
            float2 e = EiT2[k*32 + lane]; xn.x += e.x * tk; xn.y += e.y * tk;
        }
        __syncwarp();
        ((float2*)myX)[lane] = xn;
        __syncwarp();
        // ---- y = x_new@C2^T + w@D21^T + u@D22^T ----
        if (lane < 16) {
            #pragma unroll
            for (int k = 0; k < 64; k++) {
                float xk = myX[k];
                float2 c2 = C2T2[k*16 + lane]; ya.x += c2.x * xk; ya.y += c2.y * xk;
            }
            *(float2*)(optr + t * 32) = ya;
        }
    }
}

// ---------------- launch ----------------
extern "C" void kernel_launch(void* const* d_in, const int* in_sizes, int n_in,
                              void* d_out, int out_size) {
    const float* u_in = (const float*)d_in[0];
    const float* X    = (const float*)d_in[1];
    const float* Y    = (const float*)d_in[2];
    const float* B2   = (const float*)d_in[3];
    const float* C2   = (const float*)d_in[4];
    const float* D21  = (const float*)d_in[5];
    const float* D22  = (const float*)d_in[6];
    const float* D12  = (const float*)d_in[7];
    float* out = (float*)d_out;

    (void)in_sizes; (void)n_in; (void)out_size;

    // idempotent, deterministic; needed for 123 KB dynamic shared
    cudaFuncSetAttribute(ren_main, cudaFuncAttributeMaxDynamicSharedMemorySize, 123136);

    ren_precompute<<<32, 128>>>(X, Y, B2, C2, D21, D22, D12);
    ren_invert<<<1, 256>>>();
    ren_main<<<128, 256, 123136>>>(u_in, out);
}